// round 15
// baseline (speedup 1.0000x reference)
#include <cuda_runtime.h>

#define KS 7
#define TILE_W 128
#define TILE_H 64

typedef unsigned long long u64;

__device__ __forceinline__ u64 pk2(float lo, float hi) {
    u64 r; asm("mov.b64 %0, {%1,%2};" : "=l"(r) : "f"(lo), "f"(hi)); return r;
}
__device__ __forceinline__ void fma2(u64& d, u64 a, u64 b) {
    asm("fma.rn.f32x2 %0, %1, %2, %0;" : "+l"(d) : "l"(a), "l"(b));
}
__device__ __forceinline__ void unpk2(u64 v, float& lo, float& hi) {
    asm("mov.b64 {%0,%1}, %2;" : "=f"(lo), "=f"(hi) : "l"(v));
}

__global__ __launch_bounds__(512, 2)
void Conv_8443905704574_kernel(const float* __restrict__ img,
                               const float* __restrict__ ker,
                               float* __restrict__ out) {
    // padded weight rows: 8 u64 per row (64B) so every row is 16B aligned
    __shared__ __align__(16) u64 kw2[7][8];

    const int tid = threadIdx.x;
    if (tid < 56) {
        int ky = tid >> 3, kx = tid & 7;
        float w = (kx < 7) ? ker[ky * 7 + kx] : 0.0f;
        kw2[ky][kx] = pk2(w, w);
    }
    __syncthreads();             // only barrier in the kernel

    const int tx   = tid & 31;   // 4 contiguous output px per thread
    const int ty   = tid >> 5;   // 0..15
    const int bx   = blockIdx.x * TILE_W;
    const int by   = blockIdx.y * TILE_H;
    const int b    = blockIdx.z;
    const int row0 = by + ty * 4;           // first output row (global)
    const int col0 = bx + tx * 4 - 4;       // aligned read base (global), mult of 4

    // reference convolves only the LAST channel and broadcasts it
    const float* __restrict__ src = img + ((size_t)b * 3 + 2) * (size_t)(1024 * 1024);

    u64 acc01[4], acc23[4];
    #pragma unroll
    for (int o = 0; o < 4; o++) { acc01[o] = 0ull; acc23[o] = 0ull; }

    const bool xok0 = (unsigned)(col0)     < 1024u;  // false only at left image edge
    const bool xok2 = (unsigned)(col0 + 8) < 1024u;  // false only at right image edge
    // middle chunk col0+4 .. col0+7 always inside [0,1024)

    // sliding 10-row window; each input row read once, feeds up to 4 output rows
    #pragma unroll
    for (int r = 0; r < 10; r++) {
        const int gy = row0 + r - 3;
        const bool yok = (unsigned)gy < 1024u;
        const float* p = src + (size_t)(gy & 1023) * 1024 + col0;

        const float4 Z = make_float4(0.f, 0.f, 0.f, 0.f);
        float4 A0 = (yok && xok0) ? *(const float4*)(p)     : Z;
        float4 A1 =  yok          ? *(const float4*)(p + 4) : Z;
        float4 A2 = (yok && xok2) ? *(const float4*)(p + 8) : Z;

        // Pairs P[i] = (v[i+1], v[i+2]); even-start pairs are free register halves.
        ulonglong2 q0 = *(ulonglong2*)&A0;
        ulonglong2 q1 = *(ulonglong2*)&A1;
        ulonglong2 q2 = *(ulonglong2*)&A2;

        u64 P[9];
        P[0] = pk2(A0.y, A0.z);
        P[1] = q0.y;
        P[2] = pk2(A0.w, A1.x);
        P[3] = q1.x;
        P[4] = pk2(A1.y, A1.z);
        P[5] = q1.y;
        P[6] = pk2(A1.w, A2.x);
        P[7] = q2.x;
        P[8] = pk2(A2.y, A2.z);

        #pragma unroll
        for (int o = 0; o < 4; o++) {
            const int ky = r - o;
            if (ky >= 0 && ky < KS) {
                // batched weight row: 3x LDS.128 + 1x LDS.64 (broadcast)
                const u64* wr = &kw2[ky][0];
                ulonglong2 w01 = *(const ulonglong2*)(wr);
                ulonglong2 w23 = *(const ulonglong2*)(wr + 2);
                ulonglong2 w45 = *(const ulonglong2*)(wr + 4);
                u64 w6 = wr[6];

                fma2(acc01[o], P[0], w01.x);  fma2(acc23[o], P[2], w01.x);
                fma2(acc01[o], P[1], w01.y);  fma2(acc23[o], P[3], w01.y);
                fma2(acc01[o], P[2], w23.x);  fma2(acc23[o], P[4], w23.x);
                fma2(acc01[o], P[3], w23.y);  fma2(acc23[o], P[5], w23.y);
                fma2(acc01[o], P[4], w45.x);  fma2(acc23[o], P[6], w45.x);
                fma2(acc01[o], P[5], w45.y);  fma2(acc23[o], P[7], w45.y);
                fma2(acc01[o], P[6], w6);     fma2(acc23[o], P[8], w6);
            }
        }
    }

    const int ox = bx + tx * 4;
    size_t obase = (size_t)b * 3 * 1024 * 1024;
    #pragma unroll
    for (int o = 0; o < 4; o++) {
        float4 r4;
        unpk2(acc01[o], r4.x, r4.y);
        unpk2(acc23[o], r4.z, r4.w);
        size_t off = obase + (size_t)(row0 + o) * 1024 + ox;
        #pragma unroll
        for (int c = 0; c < 3; c++)
            __stcs((float4*)(out + off + (size_t)c * 1024 * 1024), r4);
    }
}

extern "C" void kernel_launch(void* const* d_in, const int* in_sizes, int n_in,
                              void* d_out, int out_size) {
    const float* img = (const float*)d_in[0];
    const float* ker = (const float*)d_in[1];
    float* out = (float*)d_out;

    dim3 grid(1024 / TILE_W, 1024 / TILE_H, 16);   // 8 x 16 x 16 = 2048 CTAs
    Conv_8443905704574_kernel<<<grid, 512>>>(img, ker, out);
}

// round 16
// speedup vs baseline: 1.0360x; 1.0360x over previous
#include <cuda_runtime.h>

#define KS 7
#define TILE_W 128
#define TILE_H 64

typedef unsigned long long u64;

__device__ __forceinline__ u64 pk2(float lo, float hi) {
    u64 r; asm("mov.b64 %0, {%1,%2};" : "=l"(r) : "f"(lo), "f"(hi)); return r;
}
__device__ __forceinline__ void fma2(u64& d, u64 a, u64 b) {
    asm("fma.rn.f32x2 %0, %1, %2, %0;" : "+l"(d) : "l"(a), "l"(b));
}
__device__ __forceinline__ void unpk2(u64 v, float& lo, float& hi) {
    asm("mov.b64 {%0,%1}, %2;" : "=f"(lo), "=f"(hi) : "l"(v));
}

__global__ __launch_bounds__(512, 2)
void Conv_8443905704574_kernel(const float* __restrict__ img,
                               const float* __restrict__ ker,
                               float* __restrict__ out) {
    // padded weight rows: 8 u64 per row (64B) so every row is 16B aligned
    __shared__ __align__(16) u64 kw2[7][8];

    const int tid = threadIdx.x;
    if (tid < 56) {
        int ky = tid >> 3, kx = tid & 7;
        float w = (kx < 7) ? ker[ky * 7 + kx] : 0.0f;
        kw2[ky][kx] = pk2(w, w);
    }
    __syncthreads();             // only barrier in the kernel

    const int tx   = tid & 31;   // 4 contiguous output px per thread
    const int ty   = tid >> 5;   // 0..15
    const int bx   = blockIdx.x * TILE_W;
    const int by   = blockIdx.y * TILE_H;
    const int b    = blockIdx.z;
    const int row0 = by + ty * 4;           // first output row (global)
    const int col0 = bx + tx * 4 - 4;       // aligned read base (global), mult of 4

    // reference convolves only the LAST channel and broadcasts it
    const float* __restrict__ src = img + ((size_t)b * 3 + 2) * (size_t)(1024 * 1024);

    u64 acc01[4], acc23[4];
    #pragma unroll
    for (int o = 0; o < 4; o++) { acc01[o] = 0ull; acc23[o] = 0ull; }

    const bool xok0 = (unsigned)(col0)     < 1024u;  // false only at left image edge
    const bool xok2 = (unsigned)(col0 + 8) < 1024u;  // false only at right image edge
    // middle chunk col0+4 .. col0+7 always inside [0,1024)

    // incremented row pointer: no per-row wide multiply; predicate guards OOB rows
    const float* p = src + (size_t)(row0 - 3) * 1024 + col0;
    int gy = row0 - 3;

    // sliding 10-row window; each input row read once, feeds up to 4 output rows
    #pragma unroll
    for (int r = 0; r < 10; r++) {
        const bool yok = (unsigned)gy < 1024u;

        const float4 Z = make_float4(0.f, 0.f, 0.f, 0.f);
        float4 A0 = (yok && xok0) ? *(const float4*)(p)     : Z;
        float4 A1 =  yok          ? *(const float4*)(p + 4) : Z;
        float4 A2 = (yok && xok2) ? *(const float4*)(p + 8) : Z;

        // Pairs P[i] = (v[i+1], v[i+2]); even-start pairs are free register halves.
        ulonglong2 q0 = *(ulonglong2*)&A0;
        ulonglong2 q1 = *(ulonglong2*)&A1;
        ulonglong2 q2 = *(ulonglong2*)&A2;

        u64 P[9];
        P[0] = pk2(A0.y, A0.z);
        P[1] = q0.y;
        P[2] = pk2(A0.w, A1.x);
        P[3] = q1.x;
        P[4] = pk2(A1.y, A1.z);
        P[5] = q1.y;
        P[6] = pk2(A1.w, A2.x);
        P[7] = q2.x;
        P[8] = pk2(A2.y, A2.z);

        #pragma unroll
        for (int o = 0; o < 4; o++) {
            const int ky = r - o;
            if (ky >= 0 && ky < KS) {
                // batched weight row: 3x LDS.128 + 1x LDS.64 (broadcast)
                const u64* wr = &kw2[ky][0];
                ulonglong2 w01 = *(const ulonglong2*)(wr);
                ulonglong2 w23 = *(const ulonglong2*)(wr + 2);
                ulonglong2 w45 = *(const ulonglong2*)(wr + 4);
                u64 w6 = wr[6];

                fma2(acc01[o], P[0], w01.x);  fma2(acc23[o], P[2], w01.x);
                fma2(acc01[o], P[1], w01.y);  fma2(acc23[o], P[3], w01.y);
                fma2(acc01[o], P[2], w23.x);  fma2(acc23[o], P[4], w23.x);
                fma2(acc01[o], P[3], w23.y);  fma2(acc23[o], P[5], w23.y);
                fma2(acc01[o], P[4], w45.x);  fma2(acc23[o], P[6], w45.x);
                fma2(acc01[o], P[5], w45.y);  fma2(acc23[o], P[7], w45.y);
                fma2(acc01[o], P[6], w6);     fma2(acc23[o], P[8], w6);
            }
        }

        p += 1024;   // next row (+4KB)
        gy += 1;
    }

    const int ox = bx + tx * 4;
    size_t obase = (size_t)b * 3 * 1024 * 1024;
    #pragma unroll
    for (int o = 0; o < 4; o++) {
        float4 r4;
        unpk2(acc01[o], r4.x, r4.y);
        unpk2(acc23[o], r4.z, r4.w);
        size_t off = obase + (size_t)(row0 + o) * 1024 + ox;
        #pragma unroll
        for (int c = 0; c < 3; c++)
            __stcs((float4*)(out + off + (size_t)c * 1024 * 1024), r4);
    }
}

extern "C" void kernel_launch(void* const* d_in, const int* in_sizes, int n_in,
                              void* d_out, int out_size) {
    const float* img = (const float*)d_in[0];
    const float* ker = (const float*)d_in[1];
    float* out = (float*)d_out;

    dim3 grid(1024 / TILE_W, 1024 / TILE_H, 16);   // 8 x 16 x 16 = 2048 CTAs
    Conv_8443905704574_kernel<<<grid, 512>>>(img, ker, out);
}